// round 1
// baseline (speedup 1.0000x reference)
#include <cuda_runtime.h>
#include <math.h>

// GMM log-likelihood: out[b] = logsumexp_k( off_k - 0.5*||L_k x_b - m_k||^2 )
//   m_k  = L_k mu_k          (precomputed, tiny)
//   off_k = log_w_k + sum_i log(L_k[i][i]) - 0.5*D*log(2*pi)
//
// Main kernel: fused K GEMMs [B,128]x[128,128]^T with square-reduce epilogue
// and online logsumexp. FFMA baseline (tensor-core tf32 version planned next).

#define NK 16
#define D 128
#define BR 128        // batch rows per block
#define ICH 64        // i-chunk (output dim chunk of L)
#define TM 8          // rows per thread
#define TI 4          // i's per thread
#define THREADS 256

#define XT_STRIDE 132 // padded (multiple of 4 floats for aligned LDS.128)
#define LT_STRIDE 68

__device__ float g_m[NK][D];
__device__ float g_off[NK];

__global__ void gmm_precompute_kernel(const float* __restrict__ means,
                                      const float* __restrict__ prec,
                                      const float* __restrict__ logw) {
    int k = blockIdx.x;
    int i = threadIdx.x;
    const float* Lk = prec + (size_t)k * D * D;
    const float* mu = means + k * D;
    float dot = 0.f;
    #pragma unroll 8
    for (int j = 0; j < D; ++j) dot += Lk[i * D + j] * mu[j];
    g_m[k][i] = dot;

    __shared__ float red[D];
    red[i] = logf(Lk[i * D + i]);
    __syncthreads();
    for (int off = D / 2; off > 0; off >>= 1) {
        if (i < off) red[i] += red[i + off];
        __syncthreads();
    }
    if (i == 0) {
        // -0.5 * D * log(2*pi) = -64 * 1.8378770664093453
        g_off[k] = logw[k] + red[0] - 64.0f * 1.8378770664093453f;
    }
}

extern __shared__ float smem_dyn[];

__global__ __launch_bounds__(THREADS, 1)
void gmm_main_kernel(const float* __restrict__ x,
                     const float* __restrict__ prec,
                     float* __restrict__ out) {
    float* XT   = smem_dyn;                     // [D][XT_STRIDE]
    float* LT   = XT + D * XT_STRIDE;           // [D][LT_STRIDE]
    float* SRED = LT + D * LT_STRIDE;           // [16][BR]

    const int tid  = threadIdx.x;
    const int row0 = blockIdx.x * BR;

    // ---- Stage X tile transposed: XT[j][r] = x[row0+r][j] ----
    {
        const float4* xg = (const float4*)(x + (size_t)row0 * D);
        #pragma unroll
        for (int it = 0; it < (BR * D / 4) / THREADS; ++it) {
            int f4 = tid + it * THREADS;
            int r  = f4 >> 5;            // 32 float4 per row
            int j0 = (f4 & 31) * 4;
            float4 v = xg[f4];
            XT[(j0 + 0) * XT_STRIDE + r] = v.x;
            XT[(j0 + 1) * XT_STRIDE + r] = v.y;
            XT[(j0 + 2) * XT_STRIDE + r] = v.z;
            XT[(j0 + 3) * XT_STRIDE + r] = v.w;
        }
    }

    const int tr    = tid & 15;          // 16 row-groups of TM=8
    const int ti    = tid >> 4;          // 16 i-groups of TI=4
    const int rbase = tr * TM;

    float m_run = -INFINITY;
    float e_run = 0.f;

    for (int k = 0; k < NK; ++k) {
        float sreg[TM];
        #pragma unroll
        for (int a = 0; a < TM; ++a) sreg[a] = 0.f;

        #pragma unroll
        for (int ch = 0; ch < D / ICH; ++ch) {
            // ---- Stage L chunk transposed: LT[j][i] = L_k[ch*ICH+i][j] ----
            __syncthreads();   // protect LT reuse (and XT/SRED on first iter)
            {
                const float4* lg =
                    (const float4*)(prec + ((size_t)k * D + ch * ICH) * D);
                #pragma unroll
                for (int it = 0; it < (ICH * D / 4) / THREADS; ++it) {
                    int f4 = tid + it * THREADS;
                    int i  = f4 >> 5;
                    int j0 = (f4 & 31) * 4;
                    float4 v = lg[f4];
                    LT[(j0 + 0) * LT_STRIDE + i] = v.x;
                    LT[(j0 + 1) * LT_STRIDE + i] = v.y;
                    LT[(j0 + 2) * LT_STRIDE + i] = v.z;
                    LT[(j0 + 3) * LT_STRIDE + i] = v.w;
                }
            }
            __syncthreads();

            // ---- Microtile accumulate: y[r][i] = sum_j L[i][j]*x[r][j] - m[i] ----
            const int ibase = ch * ICH + ti * TI;
            float mneg[TI];
            #pragma unroll
            for (int b = 0; b < TI; ++b) mneg[b] = -g_m[k][ibase + b];

            float acc[TM][TI];
            #pragma unroll
            for (int a = 0; a < TM; ++a)
                #pragma unroll
                for (int b = 0; b < TI; ++b) acc[a][b] = mneg[b];

            #pragma unroll 4
            for (int j = 0; j < D; ++j) {
                float4 xa = *(const float4*)&XT[j * XT_STRIDE + rbase];
                float4 xb = *(const float4*)&XT[j * XT_STRIDE + rbase + 4];
                float4 lv = *(const float4*)&LT[j * LT_STRIDE + ti * TI];
                float xv[TM] = {xa.x, xa.y, xa.z, xa.w, xb.x, xb.y, xb.z, xb.w};
                float lw[TI] = {lv.x, lv.y, lv.z, lv.w};
                #pragma unroll
                for (int a = 0; a < TM; ++a)
                    #pragma unroll
                    for (int b = 0; b < TI; ++b)
                        acc[a][b] = fmaf(xv[a], lw[b], acc[a][b]);
            }

            #pragma unroll
            for (int a = 0; a < TM; ++a) {
                float s = 0.f;
                #pragma unroll
                for (int b = 0; b < TI; ++b) s = fmaf(acc[a][b], acc[a][b], s);
                sreg[a] += s;
            }
        }

        // ---- Reduce partial squared-sums across the 16 ti-groups ----
        #pragma unroll
        for (int a = 0; a < TM; ++a)
            SRED[ti * BR + rbase + a] = sreg[a];
        __syncthreads();

        if (tid < BR) {
            float s = 0.f;
            #pragma unroll
            for (int t = 0; t < 16; ++t) s += SRED[t * BR + tid];
            float v = g_off[k] - 0.5f * s;
            // online logsumexp
            if (v > m_run) {
                e_run = e_run * expf(m_run - v) + 1.f;
                m_run = v;
            } else {
                e_run += expf(v - m_run);
            }
        }
        // SRED is next written only after the next chunk's leading barrier,
        // which every thread (incl. readers above) must reach first.
    }

    if (tid < BR) out[row0 + tid] = m_run + logf(e_run);
}

extern "C" void kernel_launch(void* const* d_in, const int* in_sizes, int n_in,
                              void* d_out, int out_size) {
    const float* x     = (const float*)d_in[0];  // [B, 128]
    const float* means = (const float*)d_in[1];  // [16, 128]
    const float* prec  = (const float*)d_in[2];  // [16, 128, 128]
    const float* logw  = (const float*)d_in[3];  // [16]
    float* out = (float*)d_out;

    const int B = in_sizes[0] / D;

    gmm_precompute_kernel<<<NK, D>>>(means, prec, logw);

    const size_t SMEM =
        (size_t)(D * XT_STRIDE + D * LT_STRIDE + 16 * BR) * sizeof(float);
    cudaFuncSetAttribute(gmm_main_kernel,
                         cudaFuncAttributeMaxDynamicSharedMemorySize, (int)SMEM);
    gmm_main_kernel<<<B / BR, THREADS, SMEM>>>(x, prec, out);
}

// round 4
// speedup vs baseline: 10.4330x; 10.4330x over previous
#include <cuda_runtime.h>
#include <cuda_fp16.h>
#include <math.h>
#include <stdint.h>

// GMM log-likelihood via mma.sync (sm_100 baseline PTX, legacy tensor path).
// out[b] = logsumexp_k( off_k - 0.5*||L_k x_b - m_k||^2 ), m_k = L_k mu_k.
// fp16 inputs (same 10-bit mantissa as tf32), fp32 accumulate.
// Per block: 128 batch rows; per pass: 2 components (Y = X * L^T, 128x256x128).
// 8 warps = 2(M) x 4(N); warp tile 64x64; L double-buffered via cp.async.

#define NK 16
#define D 128
#define BR 128
#define THREADS 256
#define PASSES 8

#define XS_BYTES 272                     // smem row stride: 136 halves
#define SM_X 0                           // 128 * 272 = 34816
#define SM_L 34816
#define LBUF_BYTES (256 * XS_BYTES)      // 69632 (2 comps)
#define SM_M (SM_L + 2 * LBUF_BYTES)     // 174080 : float m[16][128]
#define SM_OFFS (SM_M + NK * D * 4)      // 182272 : float off[16]
#define SM_SRED (SM_OFFS + 64)           // 182336 : float sred[2][2][128]
#define SM_TOTAL (SM_SRED + 2 * 2 * 128 * 4)  // 184384

__device__ __half g_Lh[NK * D * D];
__device__ float g_m[NK][D];
__device__ float g_off[NK];

// ---------------- prep kernels ----------------
__global__ void gmm_precompute_kernel(const float* __restrict__ means,
                                      const float* __restrict__ prec,
                                      const float* __restrict__ logw) {
    int k = blockIdx.x;
    int i = threadIdx.x;
    const float* Lk = prec + (size_t)k * D * D;
    const float* mu = means + k * D;
    float dot = 0.f;
    #pragma unroll 8
    for (int j = 0; j < D; ++j) dot += Lk[i * D + j] * mu[j];
    g_m[k][i] = dot;

    __shared__ float red[D];
    red[i] = logf(Lk[i * D + i]);
    __syncthreads();
    for (int off = D / 2; off > 0; off >>= 1) {
        if (i < off) red[i] += red[i + off];
        __syncthreads();
    }
    if (i == 0)
        g_off[k] = logw[k] + red[0] - 64.0f * 1.8378770664093453f;
}

__global__ void gmm_cvt_kernel(const float* __restrict__ prec) {
    int idx = blockIdx.x * blockDim.x + threadIdx.x;   // float4 index
    float4 v = ((const float4*)prec)[idx];
    __half2 h0 = __floats2half2_rn(v.x, v.y);
    __half2 h1 = __floats2half2_rn(v.z, v.w);
    uint2 o = make_uint2(*(uint32_t*)&h0, *(uint32_t*)&h1);
    ((uint2*)g_Lh)[idx] = o;
}

// ---------------- asm helpers ----------------
__device__ __forceinline__ uint32_t smem_u32(const void* p) {
    uint32_t a;
    asm("{ .reg .u64 t; cvta.to.shared.u64 t, %1; cvt.u32.u64 %0, t; }"
        : "=r"(a) : "l"(p));
    return a;
}
__device__ __forceinline__ void ldsm_x4(uint32_t& r0, uint32_t& r1,
                                        uint32_t& r2, uint32_t& r3,
                                        uint32_t addr) {
    asm volatile("ldmatrix.sync.aligned.m8n8.x4.shared.b16 {%0,%1,%2,%3}, [%4];"
                 : "=r"(r0), "=r"(r1), "=r"(r2), "=r"(r3) : "r"(addr));
}
__device__ __forceinline__ void mma_f16(float* c, uint32_t a0, uint32_t a1,
                                        uint32_t a2, uint32_t a3,
                                        uint32_t b0, uint32_t b1) {
    asm volatile(
        "mma.sync.aligned.m16n8k16.row.col.f32.f16.f16.f32 "
        "{%0,%1,%2,%3}, {%4,%5,%6,%7}, {%8,%9}, {%0,%1,%2,%3};"
        : "+f"(c[0]), "+f"(c[1]), "+f"(c[2]), "+f"(c[3])
        : "r"(a0), "r"(a1), "r"(a2), "r"(a3), "r"(b0), "r"(b1));
}
__device__ __forceinline__ void cp16(uint32_t dst, const void* src) {
    asm volatile("cp.async.cg.shared.global [%0], [%1], 16;"
                 :: "r"(dst), "l"(src) : "memory");
}

extern __shared__ char smem[];

__global__ __launch_bounds__(THREADS, 1)
void gmm_f16_kernel(const float* __restrict__ x, float* __restrict__ out) {
    const int tid = threadIdx.x;
    const int wid = tid >> 5;
    const int lane = tid & 31;
    const int wm = wid >> 2;          // 0..1 : row half
    const int wn = wid & 3;           // 0..3 : (comp, col half)
    const uint32_t sbase = smem_u32(smem);

    // --- prefetch L pass 0 ---
    {
        const char* src = (const char*)g_Lh;
        uint32_t dstb = sbase + SM_L;
        #pragma unroll
        for (int i = 0; i < 16; ++i) {
            int idx = tid + i * THREADS;
            int r = idx >> 4, c = idx & 15;
            cp16(dstb + r * XS_BYTES + c * 16, src + r * 256 + c * 16);
        }
        asm volatile("cp.async.commit_group;" ::: "memory");
    }

    // --- stage X (fp32 -> fp16) ---
    {
        const float4* xg = (const float4*)(x + (size_t)blockIdx.x * BR * D);
        #pragma unroll
        for (int i = 0; i < 16; ++i) {
            int f = tid + i * THREADS;
            float4 v = xg[f];
            __half2 h0 = __floats2half2_rn(v.x, v.y);
            __half2 h1 = __floats2half2_rn(v.z, v.w);
            int r = f >> 5, c4 = f & 31;
            uint2 o = make_uint2(*(uint32_t*)&h0, *(uint32_t*)&h1);
            *(uint2*)(smem + SM_X + r * XS_BYTES + c4 * 8) = o;
        }
    }
    // --- stage m, off ---
    {
        const float* gm = (const float*)g_m;
        for (int i = tid; i < NK * D; i += THREADS)
            ((float*)(smem + SM_M))[i] = gm[i];
        if (tid < NK) ((float*)(smem + SM_OFFS))[tid] = g_off[tid];
    }

    // lane offsets for ldmatrix
    const uint32_t a_lane = (uint32_t)((lane & 15) * XS_BYTES + (lane >> 4) * 16);
    const uint32_t b_lane = (uint32_t)(((lane >> 4) * 8 + (lane & 7)) * XS_BYTES +
                                       ((lane >> 3) & 1) * 16);
    const uint32_t aw = sbase + SM_X + wm * 64 * XS_BYTES + a_lane;
    const uint32_t lwoff = ((wn >> 1) * 128 + (wn & 1) * 64) * XS_BYTES + b_lane;

    float m_run = -INFINITY;
    float e_run = 0.f;

    for (int p = 0; p < PASSES; ++p) {
        if (p + 1 < PASSES) {
            const char* src = (const char*)g_Lh + (size_t)(p + 1) * 65536;
            uint32_t dstb = sbase + SM_L + ((p + 1) & 1) * LBUF_BYTES;
            #pragma unroll
            for (int i = 0; i < 16; ++i) {
                int idx = tid + i * THREADS;
                int r = idx >> 4, c = idx & 15;
                cp16(dstb + r * XS_BYTES + c * 16, src + r * 256 + c * 16);
            }
            asm volatile("cp.async.commit_group;" ::: "memory");
            asm volatile("cp.async.wait_group 1;" ::: "memory");
        } else {
            asm volatile("cp.async.wait_group 0;" ::: "memory");
        }
        __syncthreads();   // L[p] + X + m ready; prev SRED readers done

        const uint32_t lb = sbase + SM_L + (p & 1) * LBUF_BYTES + lwoff;

        float acc[4][8][4];
        #pragma unroll
        for (int mf = 0; mf < 4; ++mf)
            #pragma unroll
            for (int nf = 0; nf < 8; ++nf)
                #pragma unroll
                for (int q = 0; q < 4; ++q) acc[mf][nf][q] = 0.f;

        #pragma unroll
        for (int s = 0; s < 8; ++s) {
            uint32_t a[4][4];
            #pragma unroll
            for (int mf = 0; mf < 4; ++mf)
                ldsm_x4(a[mf][0], a[mf][1], a[mf][2], a[mf][3],
                        aw + mf * (16 * XS_BYTES) + s * 32);
            #pragma unroll
            for (int nf2 = 0; nf2 < 4; ++nf2) {
                uint32_t b0, b1, b2, b3;
                ldsm_x4(b0, b1, b2, b3, lb + nf2 * (16 * XS_BYTES) + s * 32);
                #pragma unroll
                for (int mf = 0; mf < 4; ++mf) {
                    mma_f16(acc[mf][2 * nf2],
                            a[mf][0], a[mf][1], a[mf][2], a[mf][3], b0, b1);
                    mma_f16(acc[mf][2 * nf2 + 1],
                            a[mf][0], a[mf][1], a[mf][2], a[mf][3], b2, b3);
                }
            }
        }

        // --- epilogue: subtract m, square, reduce ---
        const int comp_loc = wn >> 1;
        const float* m_comp =
            (const float*)(smem + SM_M) + (2 * p + comp_loc) * D;
        const int colb = (wn & 1) * 64 + (lane & 3) * 2;
        float* sredw = (float*)(smem + SM_SRED) + comp_loc * 256 + (wn & 1) * 128;
        #pragma unroll
        for (int mf = 0; mf < 4; ++mf) {
            float rlo = 0.f, rhi = 0.f;
            #pragma unroll
            for (int nf = 0; nf < 8; ++nf) {
                float2 mv = *(const float2*)(m_comp + colb + nf * 8);
                float v0 = acc[mf][nf][0] - mv.x;
                float v1 = acc[mf][nf][1] - mv.y;
                float v2 = acc[mf][nf][2] - mv.x;
                float v3 = acc[mf][nf][3] - mv.y;
                rlo = fmaf(v0, v0, fmaf(v1, v1, rlo));
                rhi = fmaf(v2, v2, fmaf(v3, v3, rhi));
            }
            rlo += __shfl_xor_sync(~0u, rlo, 1);
            rlo += __shfl_xor_sync(~0u, rlo, 2);
            rhi += __shfl_xor_sync(~0u, rhi, 1);
            rhi += __shfl_xor_sync(~0u, rhi, 2);
            if ((lane & 3) == 0) {
                int row = wm * 64 + mf * 16 + (lane >> 2);
                sredw[row] = rlo;
                sredw[row + 8] = rhi;
            }
        }
        __syncthreads();   // SRED complete

        if (tid < 128) {
            const float* sred = (const float*)(smem + SM_SRED);
            const float* offs = (const float*)(smem + SM_OFFS);
            #pragma unroll
            for (int c = 0; c < 2; ++c) {
                float sum = sred[c * 256 + tid] + sred[c * 256 + 128 + tid];
                float v = offs[2 * p + c] - 0.5f * sum;
                if (v > m_run) {
                    e_run = e_run * expf(m_run - v) + 1.f;
                    m_run = v;
                } else {
                    e_run += expf(v - m_run);
                }
            }
        }
        // SRED rewritten only after next pass's leading __syncthreads.
    }

    if (tid < 128)
        out[blockIdx.x * BR + tid] = m_run + logf(e_run);
}

extern "C" void kernel_launch(void* const* d_in, const int* in_sizes, int n_in,
                              void* d_out, int out_size) {
    const float* x     = (const float*)d_in[0];  // [B, 128]
    const float* means = (const float*)d_in[1];  // [16, 128]
    const float* prec  = (const float*)d_in[2];  // [16, 128, 128]
    const float* logw  = (const float*)d_in[3];  // [16]
    float* out = (float*)d_out;

    const int B = in_sizes[0] / D;

    gmm_precompute_kernel<<<NK, D>>>(means, prec, logw);
    gmm_cvt_kernel<<<NK * D * D / 4 / 256, 256>>>(prec);

    cudaFuncSetAttribute(gmm_f16_kernel,
                         cudaFuncAttributeMaxDynamicSharedMemorySize, SM_TOTAL);
    gmm_f16_kernel<<<B / BR, THREADS, SM_TOTAL>>>(x, out);
}

// round 5
// speedup vs baseline: 13.2157x; 1.2667x over previous
#include <cuda_runtime.h>
#include <cuda_fp16.h>
#include <math.h>
#include <stdint.h>

// GMM log-likelihood via mma.sync fp16 (sm_100 baseline PTX).
// out[b] = logsumexp_k( off_k - 0.5*||L_k x_b - m_k||^2 ), m_k = L_k mu_k.
// L is LOWER-TRIANGULAR: skip MMA tiles with j-chunk > i-chunk (43.75% of
// MMAs are structurally zero). i-chunks remapped per warp {0,3,4,7}/{1,2,5,6}
// so both warp groups issue exactly 18 k-chunks -> perfectly balanced.
// Per block: 128 batch rows; per pass: 2 components; L double-buffered cp.async.

#define NK 16
#define D 128
#define BR 128
#define THREADS 256
#define PASSES 8

#define XS_BYTES 272
#define SM_X 0
#define SM_L 34816
#define LBUF_BYTES (256 * XS_BYTES)
#define SM_M (SM_L + 2 * LBUF_BYTES)
#define SM_OFFS (SM_M + NK * D * 4)
#define SM_SRED (SM_OFFS + 64)
#define SM_TOTAL (SM_SRED + 2 * 2 * 128 * 4)

__device__ __half g_Lh[NK * D * D];
__device__ float g_m[NK][D];
__device__ float g_off[NK];

// ---------------- fused prep: cvt fp16 + m_k + off_k ----------------
__global__ void gmm_prep_kernel(const float* __restrict__ means,
                                const float* __restrict__ prec,
                                const float* __restrict__ logw) {
    const int k = blockIdx.x;
    const int tid = threadIdx.x;
    const int wid = tid >> 5, lane = tid & 31;
    const float* Lk = prec + (size_t)k * D * D;

    __shared__ float mu_s[D];
    __shared__ float red[D];

    if (tid < D) mu_s[tid] = means[k * D + tid];
    if (tid < D) red[tid] = logf(Lk[tid * D + tid]);

    // convert L -> fp16 (coalesced float4)
    {
        const float4* s4 = (const float4*)Lk;
        uint2* d4 = (uint2*)(g_Lh + (size_t)k * D * D);
        #pragma unroll
        for (int i = 0; i < 16; ++i) {
            float4 v = s4[tid + i * THREADS];
            __half2 h0 = __floats2half2_rn(v.x, v.y);
            __half2 h1 = __floats2half2_rn(v.z, v.w);
            d4[tid + i * THREADS] = make_uint2(*(uint32_t*)&h0, *(uint32_t*)&h1);
        }
    }
    __syncthreads();

    // m_k rows: warp per row, lane-parallel float4 + shfl reduce
    for (int r = wid; r < D; r += 8) {
        float4 v = ((const float4*)(Lk + r * D))[lane];
        float4 m4 = *(const float4*)&mu_s[lane * 4];
        float d = v.x * m4.x + v.y * m4.y + v.z * m4.z + v.w * m4.w;
        #pragma unroll
        for (int o = 16; o > 0; o >>= 1) d += __shfl_xor_sync(~0u, d, o);
        if (lane == 0) g_m[k][r] = d;
    }

    // off_k
    for (int off = D / 2; off > 0; off >>= 1) {
        if (tid < off) red[tid] += red[tid + off];
        __syncthreads();
    }
    if (tid == 0)
        g_off[k] = logw[k] + red[0] - 64.0f * 1.8378770664093453f;
}

// ---------------- asm helpers ----------------
__device__ __forceinline__ uint32_t smem_u32(const void* p) {
    uint32_t a;
    asm("{ .reg .u64 t; cvta.to.shared.u64 t, %1; cvt.u32.u64 %0, t; }"
        : "=r"(a) : "l"(p));
    return a;
}
__device__ __forceinline__ void ldsm_x4(uint32_t& r0, uint32_t& r1,
                                        uint32_t& r2, uint32_t& r3,
                                        uint32_t addr) {
    asm volatile("ldmatrix.sync.aligned.m8n8.x4.shared.b16 {%0,%1,%2,%3}, [%4];"
                 : "=r"(r0), "=r"(r1), "=r"(r2), "=r"(r3) : "r"(addr));
}
__device__ __forceinline__ void mma_f16(float* c, uint32_t a0, uint32_t a1,
                                        uint32_t a2, uint32_t a3,
                                        uint32_t b0, uint32_t b1) {
    asm volatile(
        "mma.sync.aligned.m16n8k16.row.col.f32.f16.f16.f32 "
        "{%0,%1,%2,%3}, {%4,%5,%6,%7}, {%8,%9}, {%0,%1,%2,%3};"
        : "+f"(c[0]), "+f"(c[1]), "+f"(c[2]), "+f"(c[3])
        : "r"(a0), "r"(a1), "r"(a2), "r"(a3), "r"(b0), "r"(b1));
}
__device__ __forceinline__ void cp16(uint32_t dst, const void* src) {
    asm volatile("cp.async.cg.shared.global [%0], [%1], 16;"
                 :: "r"(dst), "l"(src) : "memory");
}

// Triangular GEMM body: i-chunks I0..I3, keep k-chunk s only if s <= I.
template <int I0, int I1, int I2, int I3>
__device__ __forceinline__ void gemm_body(float acc[4][8][4], uint32_t aw,
                                          uint32_t lb) {
    constexpr int IM[4] = {I0, I1, I2, I3};
    constexpr int IMAX = (I3 > I0) ? I3 : I0;
    #pragma unroll
    for (int s = 0; s < 8; ++s) {
        if (s <= IMAX) {
            uint32_t a[4][4];
            #pragma unroll
            for (int mf = 0; mf < 4; ++mf)
                ldsm_x4(a[mf][0], a[mf][1], a[mf][2], a[mf][3],
                        aw + mf * (16 * XS_BYTES) + s * 32);
            #pragma unroll
            for (int nf2 = 0; nf2 < 4; ++nf2) {
                if (IM[nf2] >= s) {
                    uint32_t b0, b1, b2, b3;
                    ldsm_x4(b0, b1, b2, b3,
                            lb + IM[nf2] * (16 * XS_BYTES) + s * 32);
                    #pragma unroll
                    for (int mf = 0; mf < 4; ++mf) {
                        mma_f16(acc[mf][2 * nf2],
                                a[mf][0], a[mf][1], a[mf][2], a[mf][3], b0, b1);
                        mma_f16(acc[mf][2 * nf2 + 1],
                                a[mf][0], a[mf][1], a[mf][2], a[mf][3], b2, b3);
                    }
                }
            }
        }
    }
}

extern __shared__ char smem[];

__global__ __launch_bounds__(THREADS, 1)
void gmm_f16_kernel(const float* __restrict__ x, float* __restrict__ out) {
    const int tid = threadIdx.x;
    const int wid = tid >> 5;
    const int lane = tid & 31;
    const int wm = wid >> 2;
    const int wn = wid & 3;
    const int grp = wn & 1;           // i-chunk map selector
    const uint32_t sbase = smem_u32(smem);

    // --- prefetch L pass 0 ---
    {
        const char* src = (const char*)g_Lh;
        uint32_t dstb = sbase + SM_L;
        #pragma unroll
        for (int i = 0; i < 16; ++i) {
            int idx = tid + i * THREADS;
            int r = idx >> 4, c = idx & 15;
            cp16(dstb + r * XS_BYTES + c * 16, src + r * 256 + c * 16);
        }
        asm volatile("cp.async.commit_group;" ::: "memory");
    }

    // --- stage X (fp32 -> fp16) ---
    {
        const float4* xg = (const float4*)(x + (size_t)blockIdx.x * BR * D);
        #pragma unroll
        for (int i = 0; i < 16; ++i) {
            int f = tid + i * THREADS;
            float4 v = xg[f];
            __half2 h0 = __floats2half2_rn(v.x, v.y);
            __half2 h1 = __floats2half2_rn(v.z, v.w);
            int r = f >> 5, c4 = f & 31;
            *(uint2*)(smem + SM_X + r * XS_BYTES + c4 * 8) =
                make_uint2(*(uint32_t*)&h0, *(uint32_t*)&h1);
        }
    }
    // --- stage m, off ---
    {
        const float* gm = (const float*)g_m;
        for (int i = tid; i < NK * D; i += THREADS)
            ((float*)(smem + SM_M))[i] = gm[i];
        if (tid < NK) ((float*)(smem + SM_OFFS))[tid] = g_off[tid];
    }

    const uint32_t a_lane = (uint32_t)((lane & 15) * XS_BYTES + (lane >> 4) * 16);
    const uint32_t b_lane = (uint32_t)(((lane >> 4) * 8 + (lane & 7)) * XS_BYTES +
                                       ((lane >> 3) & 1) * 16);
    const uint32_t aw = sbase + SM_X + wm * 64 * XS_BYTES + a_lane;
    const uint32_t lwoff = (uint32_t)((wn >> 1) * 128 * XS_BYTES) + b_lane;

    // epilogue column map (matches gemm_body i-chunk maps)
    const int imap0 = grp ? 1 : 0, imap1 = grp ? 2 : 3;
    const int imap2 = grp ? 5 : 4, imap3 = grp ? 6 : 7;
    const int imap4[4] = {imap0, imap1, imap2, imap3};

    float m_run = -INFINITY;
    float e_run = 0.f;

    for (int p = 0; p < PASSES; ++p) {
        if (p + 1 < PASSES) {
            const char* src = (const char*)g_Lh + (size_t)(p + 1) * 65536;
            uint32_t dstb = sbase + SM_L + ((p + 1) & 1) * LBUF_BYTES;
            #pragma unroll
            for (int i = 0; i < 16; ++i) {
                int idx = tid + i * THREADS;
                int r = idx >> 4, c = idx & 15;
                cp16(dstb + r * XS_BYTES + c * 16, src + r * 256 + c * 16);
            }
            asm volatile("cp.async.commit_group;" ::: "memory");
            asm volatile("cp.async.wait_group 1;" ::: "memory");
        } else {
            asm volatile("cp.async.wait_group 0;" ::: "memory");
        }
        __syncthreads();

        const uint32_t lb = sbase + SM_L + (p & 1) * LBUF_BYTES + lwoff;

        float acc[4][8][4];
        #pragma unroll
        for (int mf = 0; mf < 4; ++mf)
            #pragma unroll
            for (int nf = 0; nf < 8; ++nf)
                #pragma unroll
                for (int q = 0; q < 4; ++q) acc[mf][nf][q] = 0.f;

        if (grp == 0) gemm_body<0, 3, 4, 7>(acc, aw, lb);
        else          gemm_body<1, 2, 5, 6>(acc, aw, lb);

        // --- epilogue: subtract m, square, reduce ---
        const int comp_loc = wn >> 1;
        const float* m_comp =
            (const float*)(smem + SM_M) + (2 * p + comp_loc) * D;
        float* sredw = (float*)(smem + SM_SRED) + comp_loc * 256 + grp * 128;
        #pragma unroll
        for (int mf = 0; mf < 4; ++mf) {
            float rlo = 0.f, rhi = 0.f;
            #pragma unroll
            for (int nf = 0; nf < 8; ++nf) {
                int col = imap4[nf >> 1] * 16 + (nf & 1) * 8 + (lane & 3) * 2;
                float2 mv = *(const float2*)(m_comp + col);
                float v0 = acc[mf][nf][0] - mv.x;
                float v1 = acc[mf][nf][1] - mv.y;
                float v2 = acc[mf][nf][2] - mv.x;
                float v3 = acc[mf][nf][3] - mv.y;
                rlo = fmaf(v0, v0, fmaf(v1, v1, rlo));
                rhi = fmaf(v2, v2, fmaf(v3, v3, rhi));
            }
            rlo += __shfl_xor_sync(~0u, rlo, 1);
            rlo += __shfl_xor_sync(~0u, rlo, 2);
            rhi += __shfl_xor_sync(~0u, rhi, 1);
            rhi += __shfl_xor_sync(~0u, rhi, 2);
            if ((lane & 3) == 0) {
                int row = wm * 64 + mf * 16 + (lane >> 2);
                sredw[row] = rlo;
                sredw[row + 8] = rhi;
            }
        }
        __syncthreads();

        if (tid < 128) {
            const float* sred = (const float*)(smem + SM_SRED);
            const float* offs = (const float*)(smem + SM_OFFS);
            #pragma unroll
            for (int c = 0; c < 2; ++c) {
                float sum = sred[c * 256 + tid] + sred[c * 256 + 128 + tid];
                float v = offs[2 * p + c] - 0.5f * sum;
                if (v > m_run) {
                    e_run = e_run * expf(m_run - v) + 1.f;
                    m_run = v;
                } else {
                    e_run += expf(v - m_run);
                }
            }
        }
    }

    if (tid < 128)
        out[blockIdx.x * BR + tid] = m_run + logf(e_run);
}

extern "C" void kernel_launch(void* const* d_in, const int* in_sizes, int n_in,
                              void* d_out, int out_size) {
    const float* x     = (const float*)d_in[0];
    const float* means = (const float*)d_in[1];
    const float* prec  = (const float*)d_in[2];
    const float* logw  = (const float*)d_in[3];
    float* out = (float*)d_out;

    const int B = in_sizes[0] / D;

    gmm_prep_kernel<<<NK, THREADS>>>(means, prec, logw);

    cudaFuncSetAttribute(gmm_f16_kernel,
                         cudaFuncAttributeMaxDynamicSharedMemorySize, SM_TOTAL);
    gmm_f16_kernel<<<B / BR, THREADS, SM_TOTAL>>>(x, out);
}

// round 6
// speedup vs baseline: 14.7299x; 1.1146x over previous
#include <cuda_runtime.h>
#include <cuda_fp16.h>
#include <math.h>
#include <stdint.h>

// GMM log-likelihood via mma.sync fp16 (sm_100 baseline PTX).
// out[b] = logsumexp_k( off_k - 0.5*||L_k x_b - m_k||^2 ), m_k = L_k mu_k.
// L lower-triangular: skip j-chunk > i-chunk tiles; i-chunks remapped per
// warp group {0,3,4,7}/{1,2,5,6} -> 18 k-chunks each (balanced).
// 512 threads / 16 warps (4 per SMSP) for latency hiding; ONE barrier per
// pass (SRED is write-once per (grp,comp,row); single logsumexp at end).

#define NK 16
#define D 128
#define BR 128
#define THREADS 512
#define PASSES 8

#define XS_BYTES 272
#define SM_X 0
#define SM_L 34816
#define LBUF_BYTES (256 * XS_BYTES)              // 69632
#define SM_M (SM_L + 2 * LBUF_BYTES)             // 174080 : float m[16][128]
#define SM_OFFS (SM_M + NK * D * 4)              // 182272 : float off[16]
#define SM_SRED (SM_OFFS + 64)                   // 182336 : float [2][16][128]
#define SM_TOTAL (SM_SRED + 2 * NK * 128 * 4)    // 198720

__device__ __half g_Lh[NK * D * D];
__device__ float g_m[NK][D];
__device__ float g_off[NK];

// ---------------- fused prep: cvt fp16 + m_k + off_k ----------------
__global__ void gmm_prep_kernel(const float* __restrict__ means,
                                const float* __restrict__ prec,
                                const float* __restrict__ logw) {
    const int k = blockIdx.x;
    const int tid = threadIdx.x;
    const int wid = tid >> 5, lane = tid & 31;
    const float* Lk = prec + (size_t)k * D * D;

    __shared__ float mu_s[D];
    __shared__ float red[D];

    if (tid < D) mu_s[tid] = means[k * D + tid];
    if (tid < D) red[tid] = logf(Lk[tid * D + tid]);

    {
        const float4* s4 = (const float4*)Lk;
        uint2* d4 = (uint2*)(g_Lh + (size_t)k * D * D);
        #pragma unroll
        for (int i = 0; i < 16; ++i) {
            float4 v = s4[tid + i * 256];
            __half2 h0 = __floats2half2_rn(v.x, v.y);
            __half2 h1 = __floats2half2_rn(v.z, v.w);
            d4[tid + i * 256] = make_uint2(*(uint32_t*)&h0, *(uint32_t*)&h1);
        }
    }
    __syncthreads();

    for (int r = wid; r < D; r += 8) {
        float4 v = ((const float4*)(Lk + r * D))[lane];
        float4 m4 = *(const float4*)&mu_s[lane * 4];
        float d = v.x * m4.x + v.y * m4.y + v.z * m4.z + v.w * m4.w;
        #pragma unroll
        for (int o = 16; o > 0; o >>= 1) d += __shfl_xor_sync(~0u, d, o);
        if (lane == 0) g_m[k][r] = d;
    }

    for (int off = D / 2; off > 0; off >>= 1) {
        if (tid < off) red[tid] += red[tid + off];
        __syncthreads();
    }
    if (tid == 0)
        g_off[k] = logw[k] + red[0] - 64.0f * 1.8378770664093453f;
}

// ---------------- asm helpers ----------------
__device__ __forceinline__ uint32_t smem_u32(const void* p) {
    uint32_t a;
    asm("{ .reg .u64 t; cvta.to.shared.u64 t, %1; cvt.u32.u64 %0, t; }"
        : "=r"(a) : "l"(p));
    return a;
}
__device__ __forceinline__ void ldsm_x4(uint32_t& r0, uint32_t& r1,
                                        uint32_t& r2, uint32_t& r3,
                                        uint32_t addr) {
    asm volatile("ldmatrix.sync.aligned.m8n8.x4.shared.b16 {%0,%1,%2,%3}, [%4];"
                 : "=r"(r0), "=r"(r1), "=r"(r2), "=r"(r3) : "r"(addr));
}
__device__ __forceinline__ void mma_f16(float* c, uint32_t a0, uint32_t a1,
                                        uint32_t a2, uint32_t a3,
                                        uint32_t b0, uint32_t b1) {
    asm volatile(
        "mma.sync.aligned.m16n8k16.row.col.f32.f16.f16.f32 "
        "{%0,%1,%2,%3}, {%4,%5,%6,%7}, {%8,%9}, {%0,%1,%2,%3};"
        : "+f"(c[0]), "+f"(c[1]), "+f"(c[2]), "+f"(c[3])
        : "r"(a0), "r"(a1), "r"(a2), "r"(a3), "r"(b0), "r"(b1));
}
__device__ __forceinline__ void cp16(uint32_t dst, const void* src) {
    asm volatile("cp.async.cg.shared.global [%0], [%1], 16;"
                 :: "r"(dst), "l"(src) : "memory");
}

// Triangular GEMM body: warp M-tile 32 rows (2 mf), i-chunks I0..I3.
template <int I0, int I1, int I2, int I3>
__device__ __forceinline__ void gemm_body(float acc[2][8][4], uint32_t aw,
                                          uint32_t lb) {
    constexpr int IM[4] = {I0, I1, I2, I3};
    constexpr int IMAX = (I3 > I0) ? I3 : I0;
    #pragma unroll
    for (int s = 0; s < 8; ++s) {
        if (s <= IMAX) {
            uint32_t a[2][4];
            #pragma unroll
            for (int mf = 0; mf < 2; ++mf)
                ldsm_x4(a[mf][0], a[mf][1], a[mf][2], a[mf][3],
                        aw + mf * (16 * XS_BYTES) + s * 32);
            #pragma unroll
            for (int nf2 = 0; nf2 < 4; ++nf2) {
                if (IM[nf2] >= s) {
                    uint32_t b0, b1, b2, b3;
                    ldsm_x4(b0, b1, b2, b3,
                            lb + IM[nf2] * (16 * XS_BYTES) + s * 32);
                    #pragma unroll
                    for (int mf = 0; mf < 2; ++mf) {
                        mma_f16(acc[mf][2 * nf2],
                                a[mf][0], a[mf][1], a[mf][2], a[mf][3], b0, b1);
                        mma_f16(acc[mf][2 * nf2 + 1],
                                a[mf][0], a[mf][1], a[mf][2], a[mf][3], b2, b3);
                    }
                }
            }
        }
    }
}

extern __shared__ char smem[];

__global__ __launch_bounds__(THREADS, 1)
void gmm_f16_kernel(const float* __restrict__ x, float* __restrict__ out) {
    const int tid = threadIdx.x;
    const int wid = tid >> 5;
    const int lane = tid & 31;
    const int wm = wid >> 2;          // 0..3 : 32-row M tile
    const int wn = wid & 3;
    const int grp = wn & 1;
    const int comp_loc = wn >> 1;
    const uint32_t sbase = smem_u32(smem);

    // --- prefetch L pass 0 ---
    {
        const char* src = (const char*)g_Lh;
        uint32_t dstb = sbase + SM_L;
        #pragma unroll
        for (int i = 0; i < 8; ++i) {
            int idx = tid + i * THREADS;
            int r = idx >> 4, c = idx & 15;
            cp16(dstb + r * XS_BYTES + c * 16, src + r * 256 + c * 16);
        }
        asm volatile("cp.async.commit_group;" ::: "memory");
    }

    // --- stage X (fp32 -> fp16) ---
    {
        const float4* xg = (const float4*)(x + (size_t)blockIdx.x * BR * D);
        #pragma unroll
        for (int i = 0; i < 8; ++i) {
            int f = tid + i * THREADS;
            float4 v = xg[f];
            __half2 h0 = __floats2half2_rn(v.x, v.y);
            __half2 h1 = __floats2half2_rn(v.z, v.w);
            int r = f >> 5, c4 = f & 31;
            *(uint2*)(smem + SM_X + r * XS_BYTES + c4 * 8) =
                make_uint2(*(uint32_t*)&h0, *(uint32_t*)&h1);
        }
    }
    // --- stage m, off ---
    {
        const float* gm = (const float*)g_m;
        #pragma unroll
        for (int i = 0; i < 4; ++i)
            ((float*)(smem + SM_M))[tid + i * THREADS] = gm[tid + i * THREADS];
        if (tid < NK) ((float*)(smem + SM_OFFS))[tid] = g_off[tid];
    }
    asm volatile("cp.async.wait_group 0;" ::: "memory");
    __syncthreads();

    const uint32_t a_lane = (uint32_t)((lane & 15) * XS_BYTES + (lane >> 4) * 16);
    const uint32_t b_lane = (uint32_t)(((lane >> 4) * 8 + (lane & 7)) * XS_BYTES +
                                       ((lane >> 3) & 1) * 16);
    const uint32_t aw = sbase + SM_X + wm * 32 * XS_BYTES + a_lane;
    const uint32_t lwoff = (uint32_t)(comp_loc * 128 * XS_BYTES) + b_lane;

    const int imap4[4] = {grp ? 1 : 0, grp ? 2 : 3, grp ? 5 : 4, grp ? 6 : 7};

    for (int p = 0; p < PASSES; ++p) {
        // prefetch L[p+1] into buf (p+1)&1 (free: last read pass p-1,
        // all warps passed the end-of-(p-1) barrier)
        if (p + 1 < PASSES) {
            const char* src = (const char*)g_Lh + (size_t)(p + 1) * 65536;
            uint32_t dstb = sbase + SM_L + ((p + 1) & 1) * LBUF_BYTES;
            #pragma unroll
            for (int i = 0; i < 8; ++i) {
                int idx = tid + i * THREADS;
                int r = idx >> 4, c = idx & 15;
                cp16(dstb + r * XS_BYTES + c * 16, src + r * 256 + c * 16);
            }
            asm volatile("cp.async.commit_group;" ::: "memory");
        }

        const uint32_t lb = sbase + SM_L + (p & 1) * LBUF_BYTES + lwoff;

        float acc[2][8][4];
        #pragma unroll
        for (int mf = 0; mf < 2; ++mf)
            #pragma unroll
            for (int nf = 0; nf < 8; ++nf)
                #pragma unroll
                for (int q = 0; q < 4; ++q) acc[mf][nf][q] = 0.f;

        if (grp == 0) gemm_body<0, 3, 4, 7>(acc, aw, lb);
        else          gemm_body<1, 2, 5, 6>(acc, aw, lb);

        // --- epilogue: subtract m, square, quad-reduce, write-once SRED ---
        const int k = 2 * p + comp_loc;
        const float* m_comp = (const float*)(smem + SM_M) + k * D;
        float* sredw = (float*)(smem + SM_SRED) + (grp * NK + k) * 128;
        #pragma unroll
        for (int mf = 0; mf < 2; ++mf) {
            float rlo = 0.f, rhi = 0.f;
            #pragma unroll
            for (int nf = 0; nf < 8; ++nf) {
                int col = imap4[nf >> 1] * 16 + (nf & 1) * 8 + (lane & 3) * 2;
                float2 mv = *(const float2*)(m_comp + col);
                float v0 = acc[mf][nf][0] - mv.x;
                float v1 = acc[mf][nf][1] - mv.y;
                float v2 = acc[mf][nf][2] - mv.x;
                float v3 = acc[mf][nf][3] - mv.y;
                rlo = fmaf(v0, v0, fmaf(v1, v1, rlo));
                rhi = fmaf(v2, v2, fmaf(v3, v3, rhi));
            }
            rlo += __shfl_xor_sync(~0u, rlo, 1);
            rlo += __shfl_xor_sync(~0u, rlo, 2);
            rhi += __shfl_xor_sync(~0u, rhi, 1);
            rhi += __shfl_xor_sync(~0u, rhi, 2);
            if ((lane & 3) == 0) {
                int row = wm * 32 + mf * 16 + (lane >> 2);
                sredw[row] = rlo;
                sredw[row + 8] = rhi;
            }
        }

        if (p + 1 < PASSES) {
            asm volatile("cp.async.wait_group 0;" ::: "memory");
            __syncthreads();   // L[p+1] visible; all reads of buf p&1 done
        }
    }

    __syncthreads();   // all SRED writes visible

    if (tid < 128) {
        const float* sred = (const float*)(smem + SM_SRED);
        const float* offs = (const float*)(smem + SM_OFFS);
        float v[NK], mx = -INFINITY;
        #pragma unroll
        for (int k = 0; k < NK; ++k) {
            float s = sred[k * 128 + tid] + sred[(NK + k) * 128 + tid];
            v[k] = offs[k] - 0.5f * s;
            mx = fmaxf(mx, v[k]);
        }
        float e = 0.f;
        #pragma unroll
        for (int k = 0; k < NK; ++k) e += expf(v[k] - mx);
        out[blockIdx.x * BR + tid] = mx + logf(e);
    }
}

extern "C" void kernel_launch(void* const* d_in, const int* in_sizes, int n_in,
                              void* d_out, int out_size) {
    const float* x     = (const float*)d_in[0];
    const float* means = (const float*)d_in[1];
    const float* prec  = (const float*)d_in[2];
    const float* logw  = (const float*)d_in[3];
    float* out = (float*)d_out;

    const int B = in_sizes[0] / D;

    gmm_prep_kernel<<<NK, 256>>>(means, prec, logw);

    cudaFuncSetAttribute(gmm_f16_kernel,
                         cudaFuncAttributeMaxDynamicSharedMemorySize, SM_TOTAL);
    gmm_f16_kernel<<<B / BR, THREADS, SM_TOTAL>>>(x, out);
}